// round 6
// baseline (speedup 1.0000x reference)
#include <cuda_runtime.h>
#include <cuda.h>
#include <cuda_bf16.h>
#include <cstdint>

// ============================================================================
// cost = sum_i relu(0.2 + u_i^T W d_i),  d = A_is - A_em, u = 0.4m + 0.6tr_m
// (bias b cancels exactly). bf16 GEMM T = D @ W^T via PORTABLE mma.sync
// (m16n8k16) — the harness PTX target is sm_103 (no 'a'), so tcgen05 is
// unavailable. cp.async double-buffered staging, ldmatrix fragments, fused
// fp32 u-dot epilogue in registers, hinge + deterministic sum.
// ============================================================================

#define B_ROWS 8192
#define E_DIM  1024
#define MT     128             // CTA M tile
#define NT     256             // CTA N tile
#define KT     64              // K per SMEM stage (128 B/row)
#define KITERS (E_DIM / KT)    // 16
#define NCHUNKS (E_DIM / NT)   // 4
#define MTILES  (B_ROWS / MT)  // 64
#define GEMM_THREADS 256

static constexpr float MARGIN = 0.2f;

// ---- static device scratch (no dynamic allocation) -------------------------
__device__ __align__(16) __nv_bfloat16 g_D[(size_t)B_ROWS * E_DIM];   // 16 MB
__device__ __align__(16) __nv_bfloat16 g_W[(size_t)E_DIM * E_DIM];    // 2 MB
__device__ float g_partial[(size_t)B_ROWS * NCHUNKS];                 // 128 KB

// ============================================================================
// Portable PTX helpers (no sm_103a-gated instructions anywhere)
// ============================================================================
__device__ __forceinline__ uint32_t smem_to_u32(const void* p) {
    uint32_t a;
    asm("{ .reg .u64 t; cvta.to.shared.u64 t, %1; cvt.u32.u64 %0, t; }"
        : "=r"(a) : "l"(p));
    return a;
}

__device__ __forceinline__ void cp_async16(uint32_t smem_addr, const void* gptr) {
    asm volatile("cp.async.cg.shared.global [%0], [%1], 16;"
                 :: "r"(smem_addr), "l"(gptr) : "memory");
}
__device__ __forceinline__ void cp_async_commit() {
    asm volatile("cp.async.commit_group;" ::: "memory");
}
template <int N>
__device__ __forceinline__ void cp_async_wait() {
    asm volatile("cp.async.wait_group %0;" :: "n"(N) : "memory");
}

__device__ __forceinline__ void ldmatrix_x4(uint32_t& r0, uint32_t& r1,
                                            uint32_t& r2, uint32_t& r3,
                                            uint32_t addr) {
    asm volatile("ldmatrix.sync.aligned.m8n8.x4.shared.b16 {%0,%1,%2,%3}, [%4];"
                 : "=r"(r0), "=r"(r1), "=r"(r2), "=r"(r3) : "r"(addr));
}

__device__ __forceinline__ void mma_16816(float* c, const uint32_t* a,
                                          const uint32_t* b) {
    asm volatile(
        "mma.sync.aligned.m16n8k16.row.col.f32.bf16.bf16.f32 "
        "{%0,%1,%2,%3}, {%4,%5,%6,%7}, {%8,%9}, {%0,%1,%2,%3};"
        : "+f"(c[0]), "+f"(c[1]), "+f"(c[2]), "+f"(c[3])
        : "r"(a[0]), "r"(a[1]), "r"(a[2]), "r"(a[3]), "r"(b[0]), "r"(b[1]));
}

// Swizzle for 128-byte rows: byte column c in row r maps to c ^ ((r&7)<<4).
__device__ __forceinline__ uint32_t swz(int row, int cbyte) {
    return (uint32_t)(row * 128 + (cbyte ^ ((row & 7) << 4)));
}

// ============================================================================
// Kernel 1: prep — D = A_is - A_em (bf16), W -> bf16
// ============================================================================
__global__ void prep_kernel(const float* __restrict__ A_is,
                            const float* __restrict__ A_em,
                            const float* __restrict__ W)
{
    const int stride = gridDim.x * blockDim.x;
    const int gtid = blockIdx.x * blockDim.x + threadIdx.x;

    const float4* a4 = (const float4*)A_is;
    const float4* e4 = (const float4*)A_em;
    __nv_bfloat162* D2 = (__nv_bfloat162*)g_D;

    const int n_vec = (B_ROWS * E_DIM) / 4;   // 2M float4
    for (int i = gtid; i < n_vec; i += stride) {
        float4 ai = a4[i], ae = e4[i];
        float4 d = make_float4(ai.x - ae.x, ai.y - ae.y, ai.z - ae.z, ai.w - ae.w);
        D2[2 * i]     = __float22bfloat162_rn(make_float2(d.x, d.y));
        D2[2 * i + 1] = __float22bfloat162_rn(make_float2(d.z, d.w));
    }

    const float4* w4 = (const float4*)W;
    __nv_bfloat162* W2 = (__nv_bfloat162*)g_W;
    const int w_vec = (E_DIM * E_DIM) / 4;    // 256K float4
    for (int i = gtid; i < w_vec; i += stride) {
        float4 w = w4[i];
        W2[2 * i]     = __float22bfloat162_rn(make_float2(w.x, w.y));
        W2[2 * i + 1] = __float22bfloat162_rn(make_float2(w.z, w.w));
    }
}

// ============================================================================
// Kernel 2: mma.sync GEMM, cp.async double buffer, fused u-dot epilogue
//   grid = (NCHUNKS=4, MTILES=64) = 256 CTAs, 256 threads (8 warps, 2x4)
//   warp tile 64(M) x 64(N): acc[4][8][4] = 128 regs
// SMEM stage: A 128x64 bf16 (16 KB) + B 256x64 bf16 (32 KB) = 48 KB, x2 = 96 KB
// ============================================================================
static constexpr int SM_A = 0;            // within stage buffer
static constexpr int SM_B = MT * 128;     // 16384
static constexpr int STAGE_BYTES = SM_B + NT * 128;  // 49152
static constexpr int SMEM_TOTAL = 2 * STAGE_BYTES;   // 98304

__global__ void __launch_bounds__(GEMM_THREADS, 1)
gemm_dot_kernel(const float* __restrict__ g_m, const float* __restrict__ g_trm)
{
    extern __shared__ char smem[];
    const uint32_t smem_base = smem_to_u32(smem);
    const int tid  = threadIdx.x;
    const int lane = tid & 31;
    const int wid  = tid >> 5;
    const int warp_m = wid >> 2;     // 0..1 (64 rows each)
    const int warp_n = wid & 3;      // 0..3 (64 cols each)
    const int nc = blockIdx.x;
    const int m0 = blockIdx.y * MT;
    const int n0 = nc * NT;

    float acc[4][8][4];
    #pragma unroll
    for (int i = 0; i < 4; i++)
        #pragma unroll
        for (int j = 0; j < 8; j++)
            #pragma unroll
            for (int k = 0; k < 4; k++) acc[i][j][k] = 0.f;

    // ---- staging: 3072 16-byte lines per stage, 12 per thread --------------
    auto issue_stage = [&](int s, int buf) {
        const int k0 = s * KT;
        const uint32_t bufbase = smem_base + buf * STAGE_BYTES;
        #pragma unroll
        for (int j = 0; j < 12; j++) {
            int idx = tid + j * GEMM_THREADS;       // 0..3071
            if (idx < 1024) {                       // A: 128 rows x 8 segs
                int row = idx >> 3, seg = idx & 7;
                const void* src = g_D + (size_t)(m0 + row) * E_DIM + k0 + seg * 8;
                cp_async16(bufbase + SM_A + swz(row, seg * 16), src);
            } else {                                // B: 256 rows x 8 segs
                int i2 = idx - 1024;
                int row = i2 >> 3, seg = i2 & 7;
                const void* src = g_W + (size_t)(n0 + row) * E_DIM + k0 + seg * 8;
                cp_async16(bufbase + SM_B + swz(row, seg * 16), src);
            }
        }
        cp_async_commit();
    };

    issue_stage(0, 0);

    #pragma unroll 1
    for (int s = 0; s < KITERS; s++) {
        if (s + 1 < KITERS) {
            issue_stage(s + 1, (s + 1) & 1);
            cp_async_wait<1>();                      // stage s complete
        } else {
            cp_async_wait<0>();
        }
        __syncthreads();

        const uint32_t bufA = smem_base + (s & 1) * STAGE_BYTES + SM_A;
        const uint32_t bufB = smem_base + (s & 1) * STAGE_BYTES + SM_B;

        #pragma unroll
        for (int ks = 0; ks < 4; ks++) {             // k-steps of 16
            uint32_t a[4][4];
            #pragma unroll
            for (int mt = 0; mt < 4; mt++) {
                int row = warp_m * 64 + mt * 16 + (lane & 15);
                int cb  = ks * 32 + ((lane >> 4) << 4);
                ldmatrix_x4(a[mt][0], a[mt][1], a[mt][2], a[mt][3],
                            bufA + swz(row, cb));
            }
            uint32_t b[8][2];
            #pragma unroll
            for (int ntp = 0; ntp < 4; ntp++) {      // pairs of n8 tiles
                int n  = warp_n * 64 + ntp * 16 + ((lane >> 4) << 3) + (lane & 7);
                int cb = ks * 32 + (((lane >> 3) & 1) << 4);
                ldmatrix_x4(b[2 * ntp][0], b[2 * ntp][1],
                            b[2 * ntp + 1][0], b[2 * ntp + 1][1],
                            bufB + swz(n, cb));
            }
            #pragma unroll
            for (int mt = 0; mt < 4; mt++)
                #pragma unroll
                for (int nt = 0; nt < 8; nt++)
                    mma_16816(acc[mt][nt], a[mt], b[nt]);
        }
        __syncthreads();                             // before buf reuse
    }

    // ---- fused epilogue: rowsum_n( T[m][n] * (0.4 m + 0.6 tr_m)[m][n] ) ----
    // C frag: {c0,c1}=row t/4, cols 2q,2q+1 ; {c2,c3}=row t/4+8.
    float* red = (float*)smem;                       // [4][128], reuse tiles
    #pragma unroll
    for (int mt = 0; mt < 4; mt++) {
        #pragma unroll
        for (int r2 = 0; r2 < 2; r2++) {
            int row_local = warp_m * 64 + mt * 16 + (lane >> 2) + r2 * 8;
            int rg = m0 + row_local;
            const float* mrow = g_m   + (size_t)rg * E_DIM;
            const float* trow = g_trm + (size_t)rg * E_DIM;
            float sum = 0.f;
            #pragma unroll
            for (int nt = 0; nt < 8; nt++) {
                int cg = n0 + warp_n * 64 + nt * 8 + ((lane & 3) << 1);
                float2 mv = *(const float2*)(mrow + cg);
                float2 tv = *(const float2*)(trow + cg);
                float u0 = 0.4f * mv.x + 0.6f * tv.x;
                float u1 = 0.4f * mv.y + 0.6f * tv.y;
                sum += acc[mt][nt][r2 * 2] * u0 + acc[mt][nt][r2 * 2 + 1] * u1;
            }
            sum += __shfl_xor_sync(0xffffffffu, sum, 1);
            sum += __shfl_xor_sync(0xffffffffu, sum, 2);
            if ((lane & 3) == 0) red[warp_n * 128 + row_local] = sum;
        }
    }
    __syncthreads();
    if (tid < 128) {
        float v = red[tid] + red[128 + tid] + red[256 + tid] + red[384 + tid];
        g_partial[(size_t)(m0 + tid) * NCHUNKS + nc] = v;
    }
}

// ============================================================================
// Kernel 3: hinge + deterministic reduction to scalar
// ============================================================================
__global__ void finish_kernel(float* __restrict__ out)
{
    __shared__ float red[1024];
    const int tid = threadIdx.x;
    float acc = 0.f;
    #pragma unroll
    for (int r = 0; r < B_ROWS / 1024; r++) {
        int row = tid + r * 1024;
        const float* p = &g_partial[(size_t)row * NCHUNKS];
        float s = MARGIN + p[0] + p[1] + p[2] + p[3];
        acc += (s > 0.f) ? s : 0.f;
    }
    red[tid] = acc;
    __syncthreads();
    #pragma unroll
    for (int off = 512; off > 0; off >>= 1) {
        if (tid < off) red[tid] += red[tid + off];
        __syncthreads();
    }
    if (tid == 0) out[0] = red[0];
}

// ============================================================================
// Launch
// ============================================================================
extern "C" void kernel_launch(void* const* d_in, const int* in_sizes, int n_in,
                              void* d_out, int out_size)
{
    const float* A_is = (const float*)d_in[0];
    const float* A_em = (const float*)d_in[1];
    const float* m    = (const float*)d_in[2];
    const float* trm  = (const float*)d_in[3];
    const float* W    = (const float*)d_in[4];
    // d_in[5] = b : cancels analytically, unused
    float* out = (float*)d_out;

    prep_kernel<<<2048, 256>>>(A_is, A_em, W);

    cudaFuncSetAttribute(gemm_dot_kernel,
                         cudaFuncAttributeMaxDynamicSharedMemorySize, SMEM_TOTAL);
    gemm_dot_kernel<<<dim3(NCHUNKS, MTILES), GEMM_THREADS, SMEM_TOTAL>>>(m, trm);

    finish_kernel<<<1, 1024>>>(out);
}